// round 4
// baseline (speedup 1.0000x reference)
#include <cuda_runtime.h>
#include <math.h>

// MonotonicSpline: y[i] = cubic uniform B-spline(clip(x[i],0,1)).
// coef[0]=c0; coef[j]=c0 + sum_{i<j}(MIN+(MAX-MIN)*sigmoid(raw_delta[i])).
// Uniform knots h=1/40 -> per-segment cubic y = ((a*u+b)*u+c)*u+d, u=frac(40x).
// Single fused kernel. Ordering: data LDGs issued first, then warp 0 builds
// the 8-way bank-replicated poly table (single-warp scan, one __syncthreads),
// then gather + Horner + store.

static constexpr int   NUM_KNOTS = 40;
static constexpr float MIN_DELTA = 0.5f / NUM_KNOTS;
static constexpr float MAX_DELTA = 3.0f / NUM_KNOTS;
static constexpr int   THREADS   = 256;
static constexpr int   ITEMS     = 4;     // float4s per thread

__device__ __forceinline__ float eval_one(float xv, const float4* __restrict__ rep,
                                          int lane8) {
    float t   = __saturatef(xv) * (float)NUM_KNOTS;   // t in [0,40]
    int   idx = min(__float2int_rz(t), NUM_KNOTS - 1);
    float u   = t - (float)idx;                        // u in [0,1]
    float4 p  = rep[idx * 8 + lane8];                  // conflict-free LDS.128
    return ((p.w * u + p.z) * u + p.y) * u + p.x;
}

__global__ void __launch_bounds__(THREADS)
spline_fused_kernel(const float* __restrict__ x,
                    const float* __restrict__ c0,
                    const float* __restrict__ raw_delta,
                    float* __restrict__ y,
                    int n4, int n) {
    __shared__ float  coef[NUM_KNOTS + 3];      // 43
    __shared__ float4 rep[NUM_KNOTS * 8];       // 8-way replicated table, 5 KB

    const int tid   = threadIdx.x;
    const int lane  = tid & 31;
    const int base  = blockIdx.x * (THREADS * ITEMS) + tid;
    const bool full = (blockIdx.x + 1) * (THREADS * ITEMS) <= n4;

    // ---- issue data loads FIRST so they overlap the table prologue ----
    float4 v[ITEMS];
    if (full) {
        #pragma unroll
        for (int it = 0; it < ITEMS; ++it)
            v[it] = reinterpret_cast<const float4*>(x)[base + it * THREADS];
    } else {
        #pragma unroll
        for (int it = 0; it < ITEMS; ++it) {
            int i = base + it * THREADS;
            if (i < n4) v[it] = reinterpret_cast<const float4*>(x)[i];
        }
    }

    // ---- warp 0: sigmoid deltas -> scan -> coef -> replicated poly table ----
    if (tid < 32) {
        const float scale = MAX_DELTA - MIN_DELTA;
        float d0 = MIN_DELTA + scale / (1.0f + __expf(-raw_delta[lane]));
        float d1 = 0.0f;
        if (lane < 10)
            d1 = MIN_DELTA + scale / (1.0f + __expf(-raw_delta[lane + 32]));
        #pragma unroll
        for (int off = 1; off < 32; off <<= 1) {
            float t0 = __shfl_up_sync(0xffffffffu, d0, off);
            float t1 = __shfl_up_sync(0xffffffffu, d1, off);
            if (lane >= off) { d0 += t0; d1 += t1; }
        }
        float tot0 = __shfl_sync(0xffffffffu, d0, 31);
        float c0v  = __ldg(c0);
        if (lane == 0) coef[0] = c0v;
        coef[lane + 1] = c0v + d0;                       // coef[1..32]
        if (lane < 10) coef[lane + 33] = c0v + tot0 + d1; // coef[33..42]
        __syncwarp();
        // fill rep[e] = poly(e>>3), e = lane, lane+32, ... (conflict-free STS.128)
        #pragma unroll
        for (int e = lane; e < NUM_KNOTS * 8; e += 32) {
            int j = e >> 3;
            float p0 = coef[j], p1 = coef[j + 1], p2 = coef[j + 2], p3 = coef[j + 3];
            float4 o;
            o.x = (p0 + 4.0f * p1 + p2) * (1.0f / 6.0f);
            o.y = (p2 - p0) * 0.5f;
            o.z = (p0 - 2.0f * p1 + p2) * 0.5f;
            o.w = (p3 - p0 + 3.0f * (p1 - p2)) * (1.0f / 6.0f);
            rep[e] = o;
        }
    }
    __syncthreads();

    // ---- gather + Horner + store ----
    const int lane8 = tid & 7;
    float4* __restrict__ y4 = reinterpret_cast<float4*>(y);
    if (full) {
        #pragma unroll
        for (int it = 0; it < ITEMS; ++it) {
            float4 o;
            o.x = eval_one(v[it].x, rep, lane8);
            o.y = eval_one(v[it].y, rep, lane8);
            o.z = eval_one(v[it].z, rep, lane8);
            o.w = eval_one(v[it].w, rep, lane8);
            y4[base + it * THREADS] = o;
        }
    } else {
        #pragma unroll
        for (int it = 0; it < ITEMS; ++it) {
            int i = base + it * THREADS;
            if (i < n4) {
                float4 o;
                o.x = eval_one(v[it].x, rep, lane8);
                o.y = eval_one(v[it].y, rep, lane8);
                o.z = eval_one(v[it].z, rep, lane8);
                o.w = eval_one(v[it].w, rep, lane8);
                y4[i] = o;
            }
        }
    }

    // scalar tail (n % 4 != 0) — block 0 only
    if (blockIdx.x == 0) {
        int j = n4 * 4 + tid;
        if (j < n) y[j] = eval_one(x[j], rep, lane8);
    }
}

extern "C" void kernel_launch(void* const* d_in, const int* in_sizes, int n_in,
                              void* d_out, int out_size) {
    const float* x         = (const float*)d_in[0];
    // d_in[1] = grid (uniform; values implied by construction)
    const float* c0        = (const float*)d_in[2];
    const float* raw_delta = (const float*)d_in[3];
    float* y = (float*)d_out;

    int n  = in_sizes[0];
    int n4 = n / 4;

    int per_block = THREADS * ITEMS;
    int blocks = (n4 + per_block - 1) / per_block;
    if (blocks == 0) blocks = 1;

    spline_fused_kernel<<<blocks, THREADS>>>(x, c0, raw_delta, y, n4, n);
}

// round 5
// speedup vs baseline: 1.0438x; 1.0438x over previous
#include <cuda_runtime.h>
#include <math.h>

// MonotonicSpline: y[i] = cubic uniform B-spline(clip(x[i],0,1)).
// coef[0]=c0; coef[j]=c0 + sum_{i<j}(MIN+(MAX-MIN)*sigmoid(raw_delta[i])).
// Uniform knots h=1/40 -> per-segment cubic y = ((a*u+b)*u+c)*u+d, u=frac(40x).
// Fused kernel, grid sized to exact residency (148 SMs x 8 blocks) with a
// grid-stride software-pipelined loop: next LDG.128 issued before computing
// the current float4. 8-way bank-replicated smem poly table (LDS.128,
// conflict-free by construction).

static constexpr int   NUM_KNOTS = 40;
static constexpr float MIN_DELTA = 0.5f / NUM_KNOTS;
static constexpr float MAX_DELTA = 3.0f / NUM_KNOTS;
static constexpr int   THREADS   = 256;
static constexpr int   MAX_BLOCKS = 148 * 8;   // one exact wave at 32 regs

__device__ __forceinline__ float eval_one(float xv, const float4* __restrict__ rep,
                                          int lane8) {
    float t   = __saturatef(xv) * (float)NUM_KNOTS;   // t in [0,40]
    int   idx = min(__float2int_rz(t), NUM_KNOTS - 1);
    float u   = t - (float)idx;                        // u in [0,1]
    float4 p  = rep[idx * 8 + lane8];                  // conflict-free LDS.128
    return ((p.w * u + p.z) * u + p.y) * u + p.x;
}

__global__ void __launch_bounds__(THREADS, 8)
spline_fused_kernel(const float* __restrict__ x,
                    const float* __restrict__ c0,
                    const float* __restrict__ raw_delta,
                    float* __restrict__ y,
                    int n4, int n) {
    __shared__ float  coef[NUM_KNOTS + 3];      // 43
    __shared__ float4 rep[NUM_KNOTS * 8];       // 8-way replicated table, 5 KB

    const int tid    = threadIdx.x;
    const int lane   = tid & 31;
    const int stride = gridDim.x * THREADS;
    const float4* __restrict__ x4 = reinterpret_cast<const float4*>(x);
    float4* __restrict__ y4 = reinterpret_cast<float4*>(y);

    // ---- issue first data load BEFORE the table prologue ----
    int i = blockIdx.x * THREADS + tid;
    float4 v;
    bool have = (i < n4);
    if (have) v = x4[i];

    // ---- warp 0: sigmoid deltas -> scan -> coef -> replicated poly table ----
    if (tid < 32) {
        const float scale = MAX_DELTA - MIN_DELTA;
        float d0 = MIN_DELTA + scale / (1.0f + __expf(-raw_delta[lane]));
        float d1 = 0.0f;
        if (lane < 10)
            d1 = MIN_DELTA + scale / (1.0f + __expf(-raw_delta[lane + 32]));
        #pragma unroll
        for (int off = 1; off < 32; off <<= 1) {
            float t0 = __shfl_up_sync(0xffffffffu, d0, off);
            float t1 = __shfl_up_sync(0xffffffffu, d1, off);
            if (lane >= off) { d0 += t0; d1 += t1; }
        }
        float tot0 = __shfl_sync(0xffffffffu, d0, 31);
        float c0v  = __ldg(c0);
        if (lane == 0) coef[0] = c0v;
        coef[lane + 1] = c0v + d0;                        // coef[1..32]
        if (lane < 10) coef[lane + 33] = c0v + tot0 + d1; // coef[33..42]
        __syncwarp();
        #pragma unroll
        for (int e = lane; e < NUM_KNOTS * 8; e += 32) {  // conflict-free STS.128
            int j = e >> 3;
            float p0 = coef[j], p1 = coef[j + 1], p2 = coef[j + 2], p3 = coef[j + 3];
            float4 o;
            o.x = (p0 + 4.0f * p1 + p2) * (1.0f / 6.0f);
            o.y = (p2 - p0) * 0.5f;
            o.z = (p0 - 2.0f * p1 + p2) * 0.5f;
            o.w = (p3 - p0 + 3.0f * (p1 - p2)) * (1.0f / 6.0f);
            rep[e] = o;
        }
    }
    __syncthreads();

    // ---- grid-stride pipelined loop: prefetch next, compute current ----
    const int lane8 = tid & 7;
    while (have) {
        int inext = i + stride;
        bool have_next = (inext < n4);
        float4 vn;
        if (have_next) vn = x4[inext];      // in flight during compute below

        float4 o;
        o.x = eval_one(v.x, rep, lane8);
        o.y = eval_one(v.y, rep, lane8);
        o.z = eval_one(v.z, rep, lane8);
        o.w = eval_one(v.w, rep, lane8);
        y4[i] = o;

        v = vn; i = inext; have = have_next;
    }

    // scalar tail (n % 4 != 0) — block 0 only
    if (blockIdx.x == 0) {
        int j = n4 * 4 + tid;
        if (j < n) y[j] = eval_one(x[j], rep, lane8);
    }
}

extern "C" void kernel_launch(void* const* d_in, const int* in_sizes, int n_in,
                              void* d_out, int out_size) {
    const float* x         = (const float*)d_in[0];
    // d_in[1] = grid (uniform; values implied by construction)
    const float* c0        = (const float*)d_in[2];
    const float* raw_delta = (const float*)d_in[3];
    float* y = (float*)d_out;

    int n  = in_sizes[0];
    int n4 = n / 4;

    int blocks = (n4 + THREADS - 1) / THREADS;
    if (blocks > MAX_BLOCKS) blocks = MAX_BLOCKS;
    if (blocks == 0) blocks = 1;

    spline_fused_kernel<<<blocks, THREADS>>>(x, c0, raw_delta, y, n4, n);
}